// round 11
// baseline (speedup 1.0000x reference)
#include <cuda_runtime.h>
#include <cuda_fp16.h>
#include <cuda/atomic>

#define T_ 64
#define S_ 400
#define B_ 32
#define H_ 512
#define E_ 1024
#define I_ 128
#define G3_ 1536
#define KSPLIT 16
#define NTHREADS 256

// ---------------- persistent device scratch ----------------
__device__ float g_Wh[(size_t)S_ * B_ * E_];      // enc @ W_h^T (fp32, precompute only)
__device__ __half g_Wh16[(size_t)S_ * B_ * E_];   // fp16 copy for P5 (26 MB)
__device__ __half g_enc16[(size_t)S_ * B_ * E_];  // fp16 copy of enc for P6 (26 MB)
__device__ float g_gi1[(size_t)T_ * B_ * G3_];    // emb @ w_ih1^T + b_ih1
__device__ float g_h[B_ * H_];
__device__ float g_s1[B_ * H_];
__device__ float g_base[B_ * E_];
__device__ float g_score[B_ * S_];
__device__ float g_cov[B_ * S_];
__device__ float g_ctx[B_ * E_];
__device__ float g_p_gh1[KSPLIT * B_ * G3_];
__device__ float g_p_base[KSPLIT * B_ * E_];
__device__ float g_p_gh2[KSPLIT * B_ * G3_];
__device__ float g_p_gi2[KSPLIT * B_ * G3_];
__device__ unsigned long long g_arrive = 0ULL;    // monotonic ticket (never reset; replay-safe)

// ---------------- math helpers ----------------
__device__ __forceinline__ float fast_tanh(float x) {
    float e = __expf(2.0f * x);
    return 1.0f - __fdividef(2.0f, e + 1.0f);
}
__device__ __forceinline__ float fast_sigmoid(float x) {
    return __fdividef(1.0f, 1.0f + __expf(-x));
}
__device__ __forceinline__ float tanh_hw(float x) {   // MUFU.TANH
    float y;
    asm("tanh.approx.f32 %0, %1;" : "=f"(y) : "f"(x));
    return y;
}

// ---------------- grid barrier: libcu++ device-scope release/acquire ----------------
__device__ __forceinline__ void gsync() {
    __syncthreads();
    if (threadIdx.x == 0) {
        cuda::atomic_ref<unsigned long long, cuda::thread_scope_device> a(g_arrive);
        unsigned long long nb = (unsigned long long)gridDim.x;
        unsigned long long tk = a.fetch_add(1ULL, cuda::memory_order_acq_rel) + 1ULL;
        unsigned long long target = ((tk + nb - 1ULL) / nb) * nb;
        while (a.load(cuda::memory_order_acquire) < target) {}
    }
    __syncthreads();
}

// ---------------- init: state, coverage, x_indexes output ----------------
__global__ void k_init(const float* __restrict__ init_state,
                       const float* __restrict__ init_cov,
                       const int* __restrict__ x_index,
                       float* __restrict__ out_xi) {
    int i = blockIdx.x * blockDim.x + threadIdx.x;
    if (i < B_ * H_) g_h[i] = init_state[i];
    if (i < B_ * S_) g_cov[i] = init_cov[i];
    for (int j = i; j < T_ * B_ * S_; j += gridDim.x * blockDim.x) {
        int s = j % S_;
        int b = (j / S_) % B_;
        out_xi[j] = (float)x_index[s * B_ + b];
    }
}

// ---------------- fp16 conversion: Wh16 from g_Wh, enc16 from enc ----------------
__global__ void k_halfify(const float* __restrict__ enc) {
    const size_t n = (size_t)S_ * B_ * E_;
    size_t i = ((size_t)blockIdx.x * blockDim.x + threadIdx.x) * 2;
    size_t stride = (size_t)gridDim.x * blockDim.x * 2;
    for (; i < n; i += stride) {
        float2 w = *(const float2*)&g_Wh[i];
        *(__half2*)&g_Wh16[i] = __floats2half2_rn(w.x, w.y);
        float2 e = *(const float2*)&enc[i];
        *(__half2*)&g_enc16[i] = __floats2half2_rn(e.x, e.y);
    }
}

// ---------------- big SGEMM (proven): C = A @ W^T (+bias), BK=16 dbl-buffered ----------------
__global__ __launch_bounds__(256) void k_sgemm_nt(
    const float* __restrict__ A, const float* __restrict__ W,
    const float* __restrict__ bias, float* __restrict__ C,
    int M, int N, int K) {
    __shared__ float As[2][16][128];
    __shared__ float Bs[2][16][128];
    const int m0 = blockIdx.y * 128;
    const int n0 = blockIdx.x * 128;
    const int tid = threadIdx.x;
    const int tm = (tid / 16) * 8;
    const int tn = (tid % 16) * 8;
    const int lr = tid >> 1;
    const int lc = (tid & 1) * 8;

    float acc[8][8];
#pragma unroll
    for (int i = 0; i < 8; i++)
#pragma unroll
        for (int j = 0; j < 8; j++) acc[i][j] = 0.0f;

    const float* Ap = A + (size_t)(m0 + lr) * K + lc;
    const float* Wp = W + (size_t)(n0 + lr) * K + lc;

    float4 pa0 = *(const float4*)(Ap + 0);
    float4 pa1 = *(const float4*)(Ap + 4);
    float4 pb0 = *(const float4*)(Wp + 0);
    float4 pb1 = *(const float4*)(Wp + 4);

    As[0][lc + 0][lr] = pa0.x; As[0][lc + 1][lr] = pa0.y; As[0][lc + 2][lr] = pa0.z; As[0][lc + 3][lr] = pa0.w;
    As[0][lc + 4][lr] = pa1.x; As[0][lc + 5][lr] = pa1.y; As[0][lc + 6][lr] = pa1.z; As[0][lc + 7][lr] = pa1.w;
    Bs[0][lc + 0][lr] = pb0.x; Bs[0][lc + 1][lr] = pb0.y; Bs[0][lc + 2][lr] = pb0.z; Bs[0][lc + 3][lr] = pb0.w;
    Bs[0][lc + 4][lr] = pb1.x; Bs[0][lc + 5][lr] = pb1.y; Bs[0][lc + 6][lr] = pb1.z; Bs[0][lc + 7][lr] = pb1.w;
    __syncthreads();

    const int nt = K / 16;
    int buf = 0;
    for (int t = 0; t < nt; t++) {
        if (t + 1 < nt) {
            int k0 = (t + 1) * 16;
            pa0 = *(const float4*)(Ap + k0);
            pa1 = *(const float4*)(Ap + k0 + 4);
            pb0 = *(const float4*)(Wp + k0);
            pb1 = *(const float4*)(Wp + k0 + 4);
        }
#pragma unroll
        for (int kk = 0; kk < 16; kk++) {
            float4 a0 = *(const float4*)&As[buf][kk][tm];
            float4 a1 = *(const float4*)&As[buf][kk][tm + 4];
            float4 b0 = *(const float4*)&Bs[buf][kk][tn];
            float4 b1 = *(const float4*)&Bs[buf][kk][tn + 4];
            float a[8] = {a0.x, a0.y, a0.z, a0.w, a1.x, a1.y, a1.z, a1.w};
            float b[8] = {b0.x, b0.y, b0.z, b0.w, b1.x, b1.y, b1.z, b1.w};
#pragma unroll
            for (int i = 0; i < 8; i++)
#pragma unroll
                for (int j = 0; j < 8; j++) acc[i][j] += a[i] * b[j];
        }
        if (t + 1 < nt) {
            int nb = buf ^ 1;
            As[nb][lc + 0][lr] = pa0.x; As[nb][lc + 1][lr] = pa0.y; As[nb][lc + 2][lr] = pa0.z; As[nb][lc + 3][lr] = pa0.w;
            As[nb][lc + 4][lr] = pa1.x; As[nb][lc + 5][lr] = pa1.y; As[nb][lc + 6][lr] = pa1.z; As[nb][lc + 7][lr] = pa1.w;
            Bs[nb][lc + 0][lr] = pb0.x; Bs[nb][lc + 1][lr] = pb0.y; Bs[nb][lc + 2][lr] = pb0.z; Bs[nb][lc + 3][lr] = pb0.w;
            Bs[nb][lc + 4][lr] = pb1.x; Bs[nb][lc + 5][lr] = pb1.y; Bs[nb][lc + 6][lr] = pb1.z; Bs[nb][lc + 7][lr] = pb1.w;
            __syncthreads();
            buf = nb;
        }
    }
    float bfrag[8];
#pragma unroll
    for (int j = 0; j < 8; j++) bfrag[j] = bias ? bias[n0 + tn + j] : 0.0f;
#pragma unroll
    for (int i = 0; i < 8; i++) {
        size_t row = (size_t)(m0 + tm + i) * N + n0 + tn;
#pragma unroll
        for (int j = 0; j < 8; j++) C[row + j] = acc[i][j] + bfrag[j];
    }
}

// ---------------- small batch-32 split-K tile (proven scalar) ----------------
__device__ __forceinline__ void small_tile(
    const float* __restrict__ X, const float* __restrict__ W,
    float* __restrict__ part, int N, int n0, int Kstride, int KC, int kc,
    float (*ws)[33], float (*xs)[36]) {
    const int k0 = kc * KC;
    const int tid = threadIdx.x;
    const int j = tid & 127;
    const int bg = tid >> 7;

    float acc[16];
#pragma unroll
    for (int u = 0; u < 16; u++) acc[u] = 0.0f;

    for (int kt = 0; kt < KC; kt += 32) {
        {
            int r = tid >> 1;
            int cb = (tid & 1) * 16;
#pragma unroll
            for (int u = 0; u < 4; u++) {
                float4 v = *(const float4*)&W[(size_t)(n0 + r) * Kstride + k0 + kt + cb + u * 4];
                ws[r][cb + u * 4 + 0] = v.x; ws[r][cb + u * 4 + 1] = v.y;
                ws[r][cb + u * 4 + 2] = v.z; ws[r][cb + u * 4 + 3] = v.w;
            }
        }
        {
            int b = tid >> 3;
            int c = (tid & 7) * 4;
            float4 v = __ldcg((const float4*)&X[(size_t)b * Kstride + k0 + kt + c]);
            xs[c + 0][b] = v.x; xs[c + 1][b] = v.y; xs[c + 2][b] = v.z; xs[c + 3][b] = v.w;
        }
        __syncthreads();
#pragma unroll
        for (int kk = 0; kk < 32; kk++) {
            float wv = ws[j][kk];
            const float4* xr = (const float4*)&xs[kk][bg * 16];
            float4 x0 = xr[0], x1 = xr[1], x2 = xr[2], x3 = xr[3];
            acc[0]  += wv * x0.x; acc[1]  += wv * x0.y; acc[2]  += wv * x0.z; acc[3]  += wv * x0.w;
            acc[4]  += wv * x1.x; acc[5]  += wv * x1.y; acc[6]  += wv * x1.z; acc[7]  += wv * x1.w;
            acc[8]  += wv * x2.x; acc[9]  += wv * x2.y; acc[10] += wv * x2.z; acc[11] += wv * x2.w;
            acc[12] += wv * x3.x; acc[13] += wv * x3.y; acc[14] += wv * x3.z; acc[15] += wv * x3.w;
        }
        __syncthreads();
    }
    float* p = part + ((size_t)kc * B_ + bg * 16) * N + n0 + j;
#pragma unroll
    for (int u = 0; u < 16; u++)
        __stcg(&p[(size_t)u * N], acc[u]);
}

// ---------------- ONE kernel per step: P1..P8 with 7 internal grid barriers ----------------
__global__ __launch_bounds__(NTHREADS, 3) void k_step(
    const float* __restrict__ enc, const float* __restrict__ x_mask,
    const float* __restrict__ y_mask,
    const float* __restrict__ W_c, const float* __restrict__ b_attn,
    const float* __restrict__ V,
    const float* __restrict__ w_hh1, const float* __restrict__ b_hh1,
    const float* __restrict__ W_s, const float* __restrict__ w_hh2,
    const float* __restrict__ b_ih2, const float* __restrict__ b_hh2,
    const float* __restrict__ w_ih2,
    float* __restrict__ out_h, float* __restrict__ out_ctx,
    float* __restrict__ out_aw, float* __restrict__ out_cov, int t) {

    __shared__ __align__(16) float sh_ws[128][33];
    __shared__ __align__(16) float sh_xs[32][36];
    __shared__ __align__(16) float sh_base[E_];
    __shared__ __align__(16) float sh_wc[E_];
    __shared__ __align__(16) float sh_v[E_];
    __shared__ float sh_aw[S_];
    __shared__ __align__(16) float4 sh_p4[NTHREADS];
    __shared__ float sh_red[8];
    __shared__ float sh_bc;

    const int tid = threadIdx.x;
    const int nb = gridDim.x;
    const int gstride = nb * NTHREADS;

    for (int i = tid; i < E_; i += NTHREADS) {
        sh_wc[i] = W_c[i];
        sh_v[i]  = V[i];
    }

    // ---- P1: gh1 partials = h @ w_hh1^T ---- (g_h from prior LAUNCH)
    for (int task = blockIdx.x; task < 12 * KSPLIT; task += nb)
        small_tile(g_h, w_hh1, g_p_gh1, G3_, (task % 12) * 128, H_, H_ / KSPLIT,
                   task / 12, sh_ws, sh_xs);
    gsync();

    // ---- P2: GRU1 finish -> s1 ----
    for (int i = blockIdx.x * NTHREADS + tid; i < B_ * H_; i += gstride) {
        int b = i / H_, idx = i % H_;
        float h = __ldcg(&g_h[i]);
        const float* gi = g_gi1 + ((size_t)t * B_ + b) * G3_;
        float gir = gi[idx], giz = gi[H_ + idx], gin = gi[2 * H_ + idx];
        float ghr = b_hh1[idx], ghz = b_hh1[H_ + idx], ghn = b_hh1[2 * H_ + idx];
#pragma unroll
        for (int c = 0; c < KSPLIT; c++) {
            const float* p = g_p_gh1 + ((size_t)c * B_ + b) * G3_;
            ghr += __ldcg(&p[idx]); ghz += __ldcg(&p[H_ + idx]); ghn += __ldcg(&p[2 * H_ + idx]);
        }
        float r = fast_sigmoid(gir + ghr);
        float z = fast_sigmoid(giz + ghz);
        float n = fast_tanh(gin + r * ghn);
        float s = (1.0f - z) * n + z * h;
        float ym = y_mask[t * B_ + b];
        __stcg(&g_s1[i], ym * s + (1.0f - ym) * h);
    }
    gsync();

    // ---- P3: dual partials: base = s1@W_s^T, gh2 = s1@w_hh2^T ----
    for (int task = blockIdx.x; task < 20 * KSPLIT; task += nb) {
        int nt = task % 20, kc = task / 20;
        if (nt < 8)
            small_tile(g_s1, W_s, g_p_base, E_, nt * 128, H_, H_ / KSPLIT, kc, sh_ws, sh_xs);
        else
            small_tile(g_s1, w_hh2, g_p_gh2, G3_, (nt - 8) * 128, H_, H_ / KSPLIT, kc, sh_ws, sh_xs);
    }
    gsync();

    // ---- P4: base reduce (+b_attn) ----
    for (int i = blockIdx.x * NTHREADS + tid; i < B_ * E_; i += gstride) {
        int b = i / E_, f = i % E_;
        float v = b_attn[f];
#pragma unroll
        for (int c = 0; c < KSPLIT; c++)
            v += __ldcg(&g_p_base[((size_t)c * B_ + b) * E_ + f]);
        __stcg(&g_base[i], v);
    }
    gsync();

    // ---- P5: attention scores (hw tanh; Wh16 fp16 stream, L2-resident) ----
    for (int task = blockIdx.x; task < B_ * 10; task += nb) {
        int b = task % B_;
        int sc = task / B_;
        for (int i = tid; i < E_; i += NTHREADS)
            sh_base[i] = __ldcg(&g_base[b * E_ + i]);
        __syncthreads();
        int warp = tid >> 5, lane = tid & 31;
        for (int si = warp; si < 40; si += 8) {
            int s = sc * 40 + si;
            float cov = __ldcg(&g_cov[b * S_ + s]);
            const __half* wh = g_Wh16 + (size_t)(s * B_ + b) * E_;
            float acc = 0.0f;
#pragma unroll
            for (int i2 = 0; i2 < 4; i2++) {
                int f8 = (i2 * 32 + lane) * 8;            // 8 halves per lane per iter
                uint4 raw = __ldcg((const uint4*)(wh + f8));
                const __half2* hp = (const __half2*)&raw;
                float2 w01 = __half22float2(hp[0]);
                float2 w23 = __half22float2(hp[1]);
                float2 w45 = __half22float2(hp[2]);
                float2 w67 = __half22float2(hp[3]);
                float4 b4a = *(const float4*)&sh_base[f8];
                float4 b4b = *(const float4*)&sh_base[f8 + 4];
                float4 c4a = *(const float4*)&sh_wc[f8];
                float4 c4b = *(const float4*)&sh_wc[f8 + 4];
                float4 v4a = *(const float4*)&sh_v[f8];
                float4 v4b = *(const float4*)&sh_v[f8 + 4];
                acc += tanh_hw(w01.x + b4a.x + cov * c4a.x) * v4a.x;
                acc += tanh_hw(w01.y + b4a.y + cov * c4a.y) * v4a.y;
                acc += tanh_hw(w23.x + b4a.z + cov * c4a.z) * v4a.z;
                acc += tanh_hw(w23.y + b4a.w + cov * c4a.w) * v4a.w;
                acc += tanh_hw(w45.x + b4b.x + cov * c4b.x) * v4b.x;
                acc += tanh_hw(w45.y + b4b.y + cov * c4b.y) * v4b.y;
                acc += tanh_hw(w67.x + b4b.z + cov * c4b.z) * v4b.z;
                acc += tanh_hw(w67.y + b4b.w + cov * c4b.w) * v4b.w;
            }
#pragma unroll
            for (int o = 16; o > 0; o >>= 1) acc += __shfl_xor_sync(0xffffffffu, acc, o);
            if (lane == 0) {
                float m = x_mask[s * B_ + b];
                __stcg(&g_score[b * S_ + s], (m == 0.0f) ? -1e9f : m * acc);
            }
        }
        __syncthreads();
    }
    gsync();

    // ---- P6: softmax + ctx (enc16 fp16 loads, L2-resident) ----
    for (int task = blockIdx.x; task < B_ * 8; task += nb) {
        int b = task >> 3, ec = task & 7;
        int lane = tid & 31, warp = tid >> 5;
        float v0 = __ldcg(&g_score[b * S_ + tid]);
        float v1 = (tid + 256 < S_) ? __ldcg(&g_score[b * S_ + tid + 256]) : -3.0e38f;
        float m = fmaxf(v0, v1);
#pragma unroll
        for (int o = 16; o > 0; o >>= 1) m = fmaxf(m, __shfl_xor_sync(0xffffffffu, m, o));
        if (lane == 0) sh_red[warp] = m;
        __syncthreads();
        if (tid == 0) {
            float x = sh_red[0];
#pragma unroll
            for (int i = 1; i < 8; i++) x = fmaxf(x, sh_red[i]);
            sh_bc = x;
        }
        __syncthreads();
        float mx = sh_bc;
        float e0 = __expf(v0 - mx);
        float e1 = (tid + 256 < S_) ? __expf(v1 - mx) : 0.0f;
        float sm = e0 + e1;
#pragma unroll
        for (int o = 16; o > 0; o >>= 1) sm += __shfl_xor_sync(0xffffffffu, sm, o);
        __syncthreads();
        if (lane == 0) sh_red[warp] = sm;
        __syncthreads();
        if (tid == 0) {
            float x = 0.0f;
#pragma unroll
            for (int i = 0; i < 8; i++) x += sh_red[i];
            sh_bc = __fdividef(1.0f, x);
        }
        __syncthreads();
        float inv = sh_bc;
        sh_aw[tid] = e0 * inv;
        if (tid + 256 < S_) sh_aw[tid + 256] = e1 * inv;
        __syncthreads();

        if (ec == 0) {
            for (int idx = tid; idx < S_; idx += NTHREADS) {
                float aw = sh_aw[idx];
                out_aw[((size_t)t * B_ + b) * S_ + idx] = aw;
                float c = __ldcg(&g_cov[b * S_ + idx]);
                out_cov[((size_t)t * B_ + b) * S_ + idx] = c;  // coverage BEFORE update
                __stcg(&g_cov[b * S_ + idx], c + aw);
            }
        }

        // ctx: 32 lanes x 4 e-values (8B fp16 loads) x 8 s-groups of 50
        int f4 = tid & 31, sg = tid >> 5;
        const __half* ebase = g_enc16 + (size_t)b * E_ + ec * 128 + f4 * 4;
        float4 acc = make_float4(0.0f, 0.0f, 0.0f, 0.0f);
        int s0 = sg * 50;
#pragma unroll 10
        for (int s = s0; s < s0 + 50; s++) {
            float a = sh_aw[s];
            uint2 raw = __ldcg((const uint2*)(ebase + (size_t)s * (B_ * E_)));
            __half2 h0 = *(const __half2*)&raw.x;
            __half2 h1 = *(const __half2*)&raw.y;
            float2 f0 = __half22float2(h0);
            float2 f1 = __half22float2(h1);
            acc.x += a * f0.x; acc.y += a * f0.y; acc.z += a * f1.x; acc.w += a * f1.y;
        }
        sh_p4[tid] = acc;
        __syncthreads();
        if (tid < 32) {
            float4 r = sh_p4[tid];
#pragma unroll
            for (int g = 1; g < 8; g++) {
                float4 q = sh_p4[g * 32 + tid];
                r.x += q.x; r.y += q.y; r.z += q.z; r.w += q.w;
            }
            int e = ec * 128 + tid * 4;
            __stcg((float4*)&g_ctx[b * E_ + e], r);
            *(float4*)&out_ctx[((size_t)t * B_ + b) * E_ + e] = r;
        }
        __syncthreads();
    }
    gsync();

    // ---- P7: gi2 partials = ctx @ w_ih2^T ----
    for (int task = blockIdx.x; task < 12 * KSPLIT; task += nb)
        small_tile(g_ctx, w_ih2, g_p_gi2, G3_, (task % 12) * 128, E_, E_ / KSPLIT,
                   task / 12, sh_ws, sh_xs);
    gsync();

    // ---- P8: GRU2 finish -> h, out_h ----
    for (int i = blockIdx.x * NTHREADS + tid; i < B_ * H_; i += gstride) {
        int b = i / H_, idx = i % H_;
        float s1 = __ldcg(&g_s1[i]);
        float gir = b_ih2[idx], giz = b_ih2[H_ + idx], gin = b_ih2[2 * H_ + idx];
        float ghr = b_hh2[idx], ghz = b_hh2[H_ + idx], ghn = b_hh2[2 * H_ + idx];
#pragma unroll
        for (int c = 0; c < KSPLIT; c++) {
            const float* pi = g_p_gi2 + ((size_t)c * B_ + b) * G3_;
            const float* ph = g_p_gh2 + ((size_t)c * B_ + b) * G3_;
            gir += __ldcg(&pi[idx]); giz += __ldcg(&pi[H_ + idx]); gin += __ldcg(&pi[2 * H_ + idx]);
            ghr += __ldcg(&ph[idx]); ghz += __ldcg(&ph[H_ + idx]); ghn += __ldcg(&ph[2 * H_ + idx]);
        }
        float r = fast_sigmoid(gir + ghr);
        float z = fast_sigmoid(giz + ghz);
        float n = fast_tanh(gin + r * ghn);
        float s = (1.0f - z) * n + z * s1;
        float ym = y_mask[t * B_ + b];
        float s2 = ym * s + (1.0f - ym) * s1;
        __stcg(&g_h[i], s2);
        out_h[((size_t)t * B_ + b) * H_ + idx] = s2;
    }
    // launch boundary provides the final sync
}

// ---------------- host launcher ----------------
extern "C" void kernel_launch(void* const* d_in, const int* in_sizes, int n_in,
                              void* d_out, int out_size) {
    const float* emb        = (const float*)d_in[0];
    const float* enc        = (const float*)d_in[1];
    const float* init_state = (const float*)d_in[2];
    const float* x_mask     = (const float*)d_in[3];
    const float* y_mask     = (const float*)d_in[4];
    const int*   x_index    = (const int*)  d_in[5];
    const float* init_cov   = (const float*)d_in[6];
    const float* W_h        = (const float*)d_in[7];
    const float* W_s        = (const float*)d_in[8];
    const float* W_c        = (const float*)d_in[9];
    const float* b_attn     = (const float*)d_in[10];
    const float* V          = (const float*)d_in[11];
    const float* w_ih1      = (const float*)d_in[12];
    const float* w_hh1      = (const float*)d_in[13];
    const float* b_ih1      = (const float*)d_in[14];
    const float* b_hh1      = (const float*)d_in[15];
    const float* w_ih2      = (const float*)d_in[16];
    const float* w_hh2      = (const float*)d_in[17];
    const float* b_ih2      = (const float*)d_in[18];
    const float* b_hh2      = (const float*)d_in[19];

    float* out     = (float*)d_out;
    float* out_h   = out;                               // (T,B,H)
    float* out_ctx = out_h + (size_t)T_ * B_ * H_;      // (T,B,E)
    float* out_aw  = out_ctx + (size_t)T_ * B_ * E_;    // (T,B,S)
    float* out_xi  = out_aw + (size_t)T_ * B_ * S_;     // (T,B,S)
    float* out_cov = out_xi + (size_t)T_ * B_ * S_;     // (T,B,S)

    float *p_Wh, *p_gi1;
    cudaGetSymbolAddress((void**)&p_Wh, g_Wh);
    cudaGetSymbolAddress((void**)&p_gi1, g_gi1);

    k_init<<<256, 256>>>(init_state, init_cov, x_index, out_xi);

    // Wh_enc = enc @ W_h^T : M=12800, N=1024, K=1024
    k_sgemm_nt<<<dim3(E_ / 128, (S_ * B_) / 128), 256>>>(enc, W_h, nullptr, p_Wh, S_ * B_, E_, E_);
    // gi1 = emb @ w_ih1^T + b_ih1 : M=2048, N=1536, K=128
    k_sgemm_nt<<<dim3(G3_ / 128, (T_ * B_) / 128), 256>>>(emb, w_ih1, b_ih1, p_gi1, T_ * B_, G3_, I_);

    // fp16 copies of Wh and enc (ordered after the Wh GEMM on the same stream)
    k_halfify<<<592, 256>>>(enc);

    // 3 co-resident blocks per SM
    int dev = 0;
    cudaGetDevice(&dev);
    int sms = 148;
    cudaDeviceGetAttribute(&sms, cudaDevAttrMultiProcessorCount, dev);
    int NB = sms * 3;

    for (int t = 0; t < T_; t++) {
        k_step<<<NB, NTHREADS>>>(enc, x_mask, y_mask, W_c, b_attn, V,
                                 w_hh1, b_hh1, W_s, w_hh2, b_ih2, b_hh2, w_ih2,
                                 out_h, out_ctx, out_aw, out_cov, t);
    }
}

// round 12
// speedup vs baseline: 1.0471x; 1.0471x over previous
#include <cuda_runtime.h>
#include <cuda/atomic>

#define T_ 64
#define S_ 400
#define B_ 32
#define H_ 512
#define E_ 1024
#define I_ 128
#define G3_ 1536
#define KSPLIT 16
#define NTHREADS 256

// ---------------- persistent device scratch ----------------
__device__ float g_Wh[(size_t)S_ * B_ * E_];      // enc @ W_h^T
__device__ float g_gi1[(size_t)T_ * B_ * G3_];    // emb @ w_ih1^T + b_ih1
__device__ float g_h[B_ * H_];
__device__ float g_s1[B_ * H_];
__device__ float g_base[B_ * E_];
__device__ float g_score[B_ * S_];
__device__ float g_cov[B_ * S_];
__device__ float g_ctx[B_ * E_];
__device__ float g_p_gh1[KSPLIT * B_ * G3_];
__device__ float g_p_base[KSPLIT * B_ * E_];
__device__ float g_p_gh2[KSPLIT * B_ * G3_];
__device__ float g_p_gi2[KSPLIT * B_ * G3_];
__device__ unsigned long long g_arrive = 0ULL;    // monotonic ticket (never reset; replay-safe)

// ---------------- math helpers ----------------
__device__ __forceinline__ float fast_tanh(float x) {
    float e = __expf(2.0f * x);
    return 1.0f - __fdividef(2.0f, e + 1.0f);
}
__device__ __forceinline__ float fast_sigmoid(float x) {
    return __fdividef(1.0f, 1.0f + __expf(-x));
}
__device__ __forceinline__ float tanh_hw(float x) {   // MUFU.TANH
    float y;
    asm("tanh.approx.f32 %0, %1;" : "=f"(y) : "f"(x));
    return y;
}

// ---------------- packed f32x2 FMA helpers (precompute GEMM only) ----------------
__device__ __forceinline__ void ffma2(unsigned long long& acc, unsigned long long a,
                                      unsigned long long b) {
    asm("fma.rn.f32x2 %0, %1, %2, %0;" : "+l"(acc) : "l"(a), "l"(b));
}
__device__ __forceinline__ unsigned long long splat2(float x) {
    unsigned long long r;
    unsigned u = __float_as_uint(x);
    asm("mov.b64 %0, {%1, %1};" : "=l"(r) : "r"(u));
    return r;
}
__device__ __forceinline__ float2 unpack2(unsigned long long v) {
    unsigned lo, hi;
    asm("mov.b64 {%0, %1}, %2;" : "=r"(lo), "=r"(hi) : "l"(v));
    return make_float2(__uint_as_float(lo), __uint_as_float(hi));
}

// ---------------- grid barrier: libcu++ device-scope release/acquire ----------------
__device__ __forceinline__ void gsync() {
    __syncthreads();
    if (threadIdx.x == 0) {
        cuda::atomic_ref<unsigned long long, cuda::thread_scope_device> a(g_arrive);
        unsigned long long nb = (unsigned long long)gridDim.x;
        unsigned long long tk = a.fetch_add(1ULL, cuda::memory_order_acq_rel) + 1ULL;
        unsigned long long target = ((tk + nb - 1ULL) / nb) * nb;
        while (a.load(cuda::memory_order_acquire) < target) {}
    }
    __syncthreads();
}

// ---------------- init: state, coverage, x_indexes output ----------------
__global__ void k_init(const float* __restrict__ init_state,
                       const float* __restrict__ init_cov,
                       const int* __restrict__ x_index,
                       float* __restrict__ out_xi) {
    int i = blockIdx.x * blockDim.x + threadIdx.x;
    if (i < B_ * H_) g_h[i] = init_state[i];
    if (i < B_ * S_) g_cov[i] = init_cov[i];
    for (int j = i; j < T_ * B_ * S_; j += gridDim.x * blockDim.x) {
        int s = j % S_;
        int b = (j / S_) % B_;
        out_xi[j] = (float)x_index[s * B_ + b];
    }
}

// ---------------- big SGEMM: C = A @ W^T (+bias), BK=16 dbl-buffered, FFMA2 ----------------
__global__ __launch_bounds__(256) void k_sgemm_nt(
    const float* __restrict__ A, const float* __restrict__ W,
    const float* __restrict__ bias, float* __restrict__ C,
    int M, int N, int K) {
    __shared__ __align__(16) float As[2][16][128];
    __shared__ __align__(16) float Bs[2][16][128];
    const int m0 = blockIdx.y * 128;
    const int n0 = blockIdx.x * 128;
    const int tid = threadIdx.x;
    const int tm = (tid / 16) * 8;
    const int tn = (tid % 16) * 8;
    const int lr = tid >> 1;
    const int lc = (tid & 1) * 8;

    unsigned long long accp[8][4];
#pragma unroll
    for (int i = 0; i < 8; i++)
#pragma unroll
        for (int j = 0; j < 4; j++) accp[i][j] = 0ULL;

    const float* Ap = A + (size_t)(m0 + lr) * K + lc;
    const float* Wp = W + (size_t)(n0 + lr) * K + lc;

    float4 pa0 = *(const float4*)(Ap + 0);
    float4 pa1 = *(const float4*)(Ap + 4);
    float4 pb0 = *(const float4*)(Wp + 0);
    float4 pb1 = *(const float4*)(Wp + 4);

    As[0][lc + 0][lr] = pa0.x; As[0][lc + 1][lr] = pa0.y; As[0][lc + 2][lr] = pa0.z; As[0][lc + 3][lr] = pa0.w;
    As[0][lc + 4][lr] = pa1.x; As[0][lc + 5][lr] = pa1.y; As[0][lc + 6][lr] = pa1.z; As[0][lc + 7][lr] = pa1.w;
    Bs[0][lc + 0][lr] = pb0.x; Bs[0][lc + 1][lr] = pb0.y; Bs[0][lc + 2][lr] = pb0.z; Bs[0][lc + 3][lr] = pb0.w;
    Bs[0][lc + 4][lr] = pb1.x; Bs[0][lc + 5][lr] = pb1.y; Bs[0][lc + 6][lr] = pb1.z; Bs[0][lc + 7][lr] = pb1.w;
    __syncthreads();

    const int nt = K / 16;
    int buf = 0;
    for (int t = 0; t < nt; t++) {
        if (t + 1 < nt) {
            int k0 = (t + 1) * 16;
            pa0 = *(const float4*)(Ap + k0);
            pa1 = *(const float4*)(Ap + k0 + 4);
            pb0 = *(const float4*)(Wp + k0);
            pb1 = *(const float4*)(Wp + k0 + 4);
        }
#pragma unroll
        for (int kk = 0; kk < 16; kk++) {
            float4 a0 = *(const float4*)&As[buf][kk][tm];
            float4 a1 = *(const float4*)&As[buf][kk][tm + 4];
            ulonglong2 b01 = *(const ulonglong2*)&Bs[buf][kk][tn];
            ulonglong2 b23 = *(const ulonglong2*)&Bs[buf][kk][tn + 4];
            unsigned long long bp0 = b01.x, bp1 = b01.y, bp2 = b23.x, bp3 = b23.y;
            float av[8] = {a0.x, a0.y, a0.z, a0.w, a1.x, a1.y, a1.z, a1.w};
#pragma unroll
            for (int i = 0; i < 8; i++) {
                unsigned long long ap = splat2(av[i]);
                ffma2(accp[i][0], ap, bp0);
                ffma2(accp[i][1], ap, bp1);
                ffma2(accp[i][2], ap, bp2);
                ffma2(accp[i][3], ap, bp3);
            }
        }
        if (t + 1 < nt) {
            int nb = buf ^ 1;
            As[nb][lc + 0][lr] = pa0.x; As[nb][lc + 1][lr] = pa0.y; As[nb][lc + 2][lr] = pa0.z; As[nb][lc + 3][lr] = pa0.w;
            As[nb][lc + 4][lr] = pa1.x; As[nb][lc + 5][lr] = pa1.y; As[nb][lc + 6][lr] = pa1.z; As[nb][lc + 7][lr] = pa1.w;
            Bs[nb][lc + 0][lr] = pb0.x; Bs[nb][lc + 1][lr] = pb0.y; Bs[nb][lc + 2][lr] = pb0.z; Bs[nb][lc + 3][lr] = pb0.w;
            Bs[nb][lc + 4][lr] = pb1.x; Bs[nb][lc + 5][lr] = pb1.y; Bs[nb][lc + 6][lr] = pb1.z; Bs[nb][lc + 7][lr] = pb1.w;
            __syncthreads();
            buf = nb;
        }
    }
    float bfrag[8];
#pragma unroll
    for (int j = 0; j < 8; j++) bfrag[j] = bias ? bias[n0 + tn + j] : 0.0f;
#pragma unroll
    for (int i = 0; i < 8; i++) {
        size_t row = (size_t)(m0 + tm + i) * N + n0 + tn;
#pragma unroll
        for (int jp = 0; jp < 4; jp++) {
            float2 f = unpack2(accp[i][jp]);
            C[row + 2 * jp]     = f.x + bfrag[2 * jp];
            C[row + 2 * jp + 1] = f.y + bfrag[2 * jp + 1];
        }
    }
}

// ---------------- small batch-32 split-K tile (proven scalar) ----------------
__device__ __forceinline__ void small_tile(
    const float* __restrict__ X, const float* __restrict__ W,
    float* __restrict__ part, int N, int n0, int Kstride, int KC, int kc,
    float (*ws)[33], float (*xs)[36]) {
    const int k0 = kc * KC;
    const int tid = threadIdx.x;
    const int j = tid & 127;
    const int bg = tid >> 7;

    float acc[16];
#pragma unroll
    for (int u = 0; u < 16; u++) acc[u] = 0.0f;

    for (int kt = 0; kt < KC; kt += 32) {
        {
            int r = tid >> 1;
            int cb = (tid & 1) * 16;
#pragma unroll
            for (int u = 0; u < 4; u++) {
                float4 v = *(const float4*)&W[(size_t)(n0 + r) * Kstride + k0 + kt + cb + u * 4];
                ws[r][cb + u * 4 + 0] = v.x; ws[r][cb + u * 4 + 1] = v.y;
                ws[r][cb + u * 4 + 2] = v.z; ws[r][cb + u * 4 + 3] = v.w;
            }
        }
        {
            int b = tid >> 3;
            int c = (tid & 7) * 4;
            float4 v = __ldcg((const float4*)&X[(size_t)b * Kstride + k0 + kt + c]);
            xs[c + 0][b] = v.x; xs[c + 1][b] = v.y; xs[c + 2][b] = v.z; xs[c + 3][b] = v.w;
        }
        __syncthreads();
#pragma unroll
        for (int kk = 0; kk < 32; kk++) {
            float wv = ws[j][kk];
            const float4* xr = (const float4*)&xs[kk][bg * 16];
            float4 x0 = xr[0], x1 = xr[1], x2 = xr[2], x3 = xr[3];
            acc[0]  += wv * x0.x; acc[1]  += wv * x0.y; acc[2]  += wv * x0.z; acc[3]  += wv * x0.w;
            acc[4]  += wv * x1.x; acc[5]  += wv * x1.y; acc[6]  += wv * x1.z; acc[7]  += wv * x1.w;
            acc[8]  += wv * x2.x; acc[9]  += wv * x2.y; acc[10] += wv * x2.z; acc[11] += wv * x2.w;
            acc[12] += wv * x3.x; acc[13] += wv * x3.y; acc[14] += wv * x3.z; acc[15] += wv * x3.w;
        }
        __syncthreads();
    }
    float* p = part + ((size_t)kc * B_ + bg * 16) * N + n0 + j;
#pragma unroll
    for (int u = 0; u < 16; u++)
        __stcg(&p[(size_t)u * N], acc[u]);
}

// ---------------- ONE kernel per step: P1..P8 with 7 internal grid barriers ----------------
__global__ __launch_bounds__(NTHREADS, 3) void k_step(
    const float* __restrict__ enc, const float* __restrict__ x_mask,
    const float* __restrict__ y_mask,
    const float* __restrict__ W_c, const float* __restrict__ b_attn,
    const float* __restrict__ V,
    const float* __restrict__ w_hh1, const float* __restrict__ b_hh1,
    const float* __restrict__ W_s, const float* __restrict__ w_hh2,
    const float* __restrict__ b_ih2, const float* __restrict__ b_hh2,
    const float* __restrict__ w_ih2,
    float* __restrict__ out_h, float* __restrict__ out_ctx,
    float* __restrict__ out_aw, float* __restrict__ out_cov, int t) {

    __shared__ __align__(16) float sh_ws[128][33];
    __shared__ __align__(16) float sh_xs[32][36];
    __shared__ __align__(16) float sh_base[E_];
    __shared__ __align__(16) float sh_wc[E_];
    __shared__ __align__(16) float sh_v[E_];
    __shared__ float sh_aw[S_];
    __shared__ __align__(16) float4 sh_p4[NTHREADS];
    __shared__ float sh_red[8];
    __shared__ float sh_bc;

    const int tid = threadIdx.x;
    const int nb = gridDim.x;
    const int gstride = nb * NTHREADS;

    for (int i = tid; i < E_; i += NTHREADS) {
        sh_wc[i] = W_c[i];
        sh_v[i]  = V[i];
    }

    // ---- P1: gh1 partials = h @ w_hh1^T ---- (g_h from prior LAUNCH)
    for (int task = blockIdx.x; task < 12 * KSPLIT; task += nb)
        small_tile(g_h, w_hh1, g_p_gh1, G3_, (task % 12) * 128, H_, H_ / KSPLIT,
                   task / 12, sh_ws, sh_xs);
    gsync();

    // ---- P2: GRU1 finish -> s1 ----
    for (int i = blockIdx.x * NTHREADS + tid; i < B_ * H_; i += gstride) {
        int b = i / H_, idx = i % H_;
        float h = __ldcg(&g_h[i]);
        const float* gi = g_gi1 + ((size_t)t * B_ + b) * G3_;
        float gir = gi[idx], giz = gi[H_ + idx], gin = gi[2 * H_ + idx];
        float ghr = b_hh1[idx], ghz = b_hh1[H_ + idx], ghn = b_hh1[2 * H_ + idx];
#pragma unroll
        for (int c = 0; c < KSPLIT; c++) {
            const float* p = g_p_gh1 + ((size_t)c * B_ + b) * G3_;
            ghr += __ldcg(&p[idx]); ghz += __ldcg(&p[H_ + idx]); ghn += __ldcg(&p[2 * H_ + idx]);
        }
        float r = fast_sigmoid(gir + ghr);
        float z = fast_sigmoid(giz + ghz);
        float n = fast_tanh(gin + r * ghn);
        float s = (1.0f - z) * n + z * h;
        float ym = y_mask[t * B_ + b];
        __stcg(&g_s1[i], ym * s + (1.0f - ym) * h);
    }
    gsync();

    // ---- P3: dual partials: base = s1@W_s^T, gh2 = s1@w_hh2^T ----
    for (int task = blockIdx.x; task < 20 * KSPLIT; task += nb) {
        int nt = task % 20, kc = task / 20;
        if (nt < 8)
            small_tile(g_s1, W_s, g_p_base, E_, nt * 128, H_, H_ / KSPLIT, kc, sh_ws, sh_xs);
        else
            small_tile(g_s1, w_hh2, g_p_gh2, G3_, (nt - 8) * 128, H_, H_ / KSPLIT, kc, sh_ws, sh_xs);
    }
    gsync();

    // ---- P4: base reduce (+b_attn) ----
    for (int i = blockIdx.x * NTHREADS + tid; i < B_ * E_; i += gstride) {
        int b = i / E_, f = i % E_;
        float v = b_attn[f];
#pragma unroll
        for (int c = 0; c < KSPLIT; c++)
            v += __ldcg(&g_p_base[((size_t)c * B_ + b) * E_ + f]);
        __stcg(&g_base[i], v);
    }
    gsync();

    // ---- P5: attention scores (hw tanh; Wh streamed evict-first) ----
    for (int task = blockIdx.x; task < B_ * 10; task += nb) {
        int b = task % B_;
        int sc = task / B_;
        for (int i = tid; i < E_; i += NTHREADS)
            sh_base[i] = __ldcg(&g_base[b * E_ + i]);
        __syncthreads();
        int warp = tid >> 5, lane = tid & 31;
        for (int si = warp; si < 40; si += 8) {
            int s = sc * 40 + si;
            float cov = __ldcg(&g_cov[b * S_ + s]);
            const float4* wh = (const float4*)&g_Wh[(size_t)(s * B_ + b) * E_];
            float acc = 0.0f;
#pragma unroll
            for (int i2 = 0; i2 < 8; i2++) {
                int f = i2 * 32 + lane;
                float4 w4 = __ldcs(&wh[f]);          // streaming: don't pollute L2
                float4 b4 = *(const float4*)&sh_base[f * 4];
                float4 c4 = *(const float4*)&sh_wc[f * 4];
                float4 v4 = *(const float4*)&sh_v[f * 4];
                acc += tanh_hw(w4.x + b4.x + cov * c4.x) * v4.x;
                acc += tanh_hw(w4.y + b4.y + cov * c4.y) * v4.y;
                acc += tanh_hw(w4.z + b4.z + cov * c4.z) * v4.z;
                acc += tanh_hw(w4.w + b4.w + cov * c4.w) * v4.w;
            }
#pragma unroll
            for (int o = 16; o > 0; o >>= 1) acc += __shfl_xor_sync(0xffffffffu, acc, o);
            if (lane == 0) {
                float m = x_mask[s * B_ + b];
                __stcg(&g_score[b * S_ + s], (m == 0.0f) ? -1e9f : m * acc);
            }
        }
        __syncthreads();
    }
    gsync();

    // ---- P6: softmax + ctx (enc L2-cached float4 loads) ----
    for (int task = blockIdx.x; task < B_ * 8; task += nb) {
        int b = task >> 3, ec = task & 7;
        int lane = tid & 31, warp = tid >> 5;
        float v0 = __ldcg(&g_score[b * S_ + tid]);
        float v1 = (tid + 256 < S_) ? __ldcg(&g_score[b * S_ + tid + 256]) : -3.0e38f;
        float m = fmaxf(v0, v1);
#pragma unroll
        for (int o = 16; o > 0; o >>= 1) m = fmaxf(m, __shfl_xor_sync(0xffffffffu, m, o));
        if (lane == 0) sh_red[warp] = m;
        __syncthreads();
        if (tid == 0) {
            float x = sh_red[0];
#pragma unroll
            for (int i = 1; i < 8; i++) x = fmaxf(x, sh_red[i]);
            sh_bc = x;
        }
        __syncthreads();
        float mx = sh_bc;
        float e0 = __expf(v0 - mx);
        float e1 = (tid + 256 < S_) ? __expf(v1 - mx) : 0.0f;
        float sm = e0 + e1;
#pragma unroll
        for (int o = 16; o > 0; o >>= 1) sm += __shfl_xor_sync(0xffffffffu, sm, o);
        __syncthreads();
        if (lane == 0) sh_red[warp] = sm;
        __syncthreads();
        if (tid == 0) {
            float x = 0.0f;
#pragma unroll
            for (int i = 0; i < 8; i++) x += sh_red[i];
            sh_bc = __fdividef(1.0f, x);
        }
        __syncthreads();
        float inv = sh_bc;
        sh_aw[tid] = e0 * inv;
        if (tid + 256 < S_) sh_aw[tid + 256] = e1 * inv;
        __syncthreads();

        if (ec == 0) {
            for (int idx = tid; idx < S_; idx += NTHREADS) {
                float aw = sh_aw[idx];
                out_aw[((size_t)t * B_ + b) * S_ + idx] = aw;
                float c = __ldcg(&g_cov[b * S_ + idx]);
                out_cov[((size_t)t * B_ + b) * S_ + idx] = c;  // coverage BEFORE update
                __stcg(&g_cov[b * S_ + idx], c + aw);
            }
        }

        // ctx: 32 float4-columns x 8 s-groups of 50
        int f4 = tid & 31, sg = tid >> 5;
        const float4* ep = (const float4*)(enc + (size_t)b * E_ + ec * 128) + f4;
        float4 acc = make_float4(0.0f, 0.0f, 0.0f, 0.0f);
        int s0 = sg * 50;
#pragma unroll 10
        for (int s = s0; s < s0 + 50; s++) {
            float a = sh_aw[s];
            float4 v = __ldcg(&ep[(size_t)s * (B_ * E_ / 4)]);
            acc.x += a * v.x; acc.y += a * v.y; acc.z += a * v.z; acc.w += a * v.w;
        }
        sh_p4[tid] = acc;
        __syncthreads();
        if (tid < 32) {
            float4 r = sh_p4[tid];
#pragma unroll
            for (int g = 1; g < 8; g++) {
                float4 q = sh_p4[g * 32 + tid];
                r.x += q.x; r.y += q.y; r.z += q.z; r.w += q.w;
            }
            int e = ec * 128 + tid * 4;
            __stcg((float4*)&g_ctx[b * E_ + e], r);
            *(float4*)&out_ctx[((size_t)t * B_ + b) * E_ + e] = r;
        }
        __syncthreads();
    }
    gsync();

    // ---- P7: gi2 partials = ctx @ w_ih2^T ----
    for (int task = blockIdx.x; task < 12 * KSPLIT; task += nb)
        small_tile(g_ctx, w_ih2, g_p_gi2, G3_, (task % 12) * 128, E_, E_ / KSPLIT,
                   task / 12, sh_ws, sh_xs);
    gsync();

    // ---- P8: GRU2 finish -> h, out_h ----
    for (int i = blockIdx.x * NTHREADS + tid; i < B_ * H_; i += gstride) {
        int b = i / H_, idx = i % H_;
        float s1 = __ldcg(&g_s1[i]);
        float gir = b_ih2[idx], giz = b_ih2[H_ + idx], gin = b_ih2[2 * H_ + idx];
        float ghr = b_hh2[idx], ghz = b_hh2[H_ + idx], ghn = b_hh2[2 * H_ + idx];
#pragma unroll
        for (int c = 0; c < KSPLIT; c++) {
            const float* pi = g_p_gi2 + ((size_t)c * B_ + b) * G3_;
            const float* ph = g_p_gh2 + ((size_t)c * B_ + b) * G3_;
            gir += __ldcg(&pi[idx]); giz += __ldcg(&pi[H_ + idx]); gin += __ldcg(&pi[2 * H_ + idx]);
            ghr += __ldcg(&ph[idx]); ghz += __ldcg(&ph[H_ + idx]); ghn += __ldcg(&ph[2 * H_ + idx]);
        }
        float r = fast_sigmoid(gir + ghr);
        float z = fast_sigmoid(giz + ghz);
        float n = fast_tanh(gin + r * ghn);
        float s = (1.0f - z) * n + z * s1;
        float ym = y_mask[t * B_ + b];
        float s2 = ym * s + (1.0f - ym) * s1;
        __stcg(&g_h[i], s2);
        out_h[((size_t)t * B_ + b) * H_ + idx] = s2;
    }
    // launch boundary provides the final sync
}

// ---------------- host launcher ----------------
extern "C" void kernel_launch(void* const* d_in, const int* in_sizes, int n_in,
                              void* d_out, int out_size) {
    const float* emb        = (const float*)d_in[0];
    const float* enc        = (const float*)d_in[1];
    const float* init_state = (const float*)d_in[2];
    const float* x_mask     = (const float*)d_in[3];
    const float* y_mask     = (const float*)d_in[4];
    const int*   x_index    = (const int*)  d_in[5];
    const float* init_cov   = (const float*)d_in[6];
    const float* W_h        = (const float*)d_in[7];
    const float* W_s        = (const float*)d_in[8];
    const float* W_c        = (const float*)d_in[9];
    const float* b_attn     = (const float*)d_in[10];
    const float* V          = (const float*)d_in[11];
    const float* w_ih1      = (const float*)d_in[12];
    const float* w_hh1      = (const float*)d_in[13];
    const float* b_ih1      = (const float*)d_in[14];
    const float* b_hh1      = (const float*)d_in[15];
    const float* w_ih2      = (const float*)d_in[16];
    const float* w_hh2      = (const float*)d_in[17];
    const float* b_ih2      = (const float*)d_in[18];
    const float* b_hh2      = (const float*)d_in[19];

    float* out     = (float*)d_out;
    float* out_h   = out;                               // (T,B,H)
    float* out_ctx = out_h + (size_t)T_ * B_ * H_;      // (T,B,E)
    float* out_aw  = out_ctx + (size_t)T_ * B_ * E_;    // (T,B,S)
    float* out_xi  = out_aw + (size_t)T_ * B_ * S_;     // (T,B,S)
    float* out_cov = out_xi + (size_t)T_ * B_ * S_;     // (T,B,S)

    float *p_Wh, *p_gi1;
    cudaGetSymbolAddress((void**)&p_Wh, g_Wh);
    cudaGetSymbolAddress((void**)&p_gi1, g_gi1);

    k_init<<<256, 256>>>(init_state, init_cov, x_index, out_xi);

    // Wh_enc = enc @ W_h^T : M=12800, N=1024, K=1024
    k_sgemm_nt<<<dim3(E_ / 128, (S_ * B_) / 128), 256>>>(enc, W_h, nullptr, p_Wh, S_ * B_, E_, E_);
    // gi1 = emb @ w_ih1^T + b_ih1 : M=2048, N=1536, K=128
    k_sgemm_nt<<<dim3(G3_ / 128, (T_ * B_) / 128), 256>>>(emb, w_ih1, b_ih1, p_gi1, T_ * B_, G3_, I_);

    // 3 co-resident blocks per SM
    int dev = 0;
    cudaGetDevice(&dev);
    int sms = 148;
    cudaDeviceGetAttribute(&sms, cudaDevAttrMultiProcessorCount, dev);
    int NB = sms * 3;

    for (int t = 0; t < T_; t++) {
        k_step<<<NB, NTHREADS>>>(enc, x_mask, y_mask, W_c, b_attn, V,
                                 w_hh1, b_hh1, W_s, w_hh2, b_ih2, b_hh2, w_ih2,
                                 out_h, out_ctx, out_aw, out_cov, t);
    }
}

// round 13
// speedup vs baseline: 1.0590x; 1.0114x over previous
#include <cuda_runtime.h>
#include <cuda/atomic>

#define T_ 64
#define S_ 400
#define B_ 32
#define H_ 512
#define E_ 1024
#define I_ 128
#define G3_ 1536
#define KSPLIT 16
#define NTHREADS 256

// ---------------- persistent device scratch ----------------
__device__ float g_Wh[(size_t)S_ * B_ * E_];      // enc @ W_h^T
__device__ float g_gi1[(size_t)T_ * B_ * G3_];    // emb @ w_ih1^T + b_ih1
__device__ float g_h[B_ * H_];
__device__ float g_s1[B_ * H_];
__device__ float g_score[B_ * S_];
__device__ float g_cov[B_ * S_];
__device__ float g_ctx[B_ * E_];
__device__ float g_p_gh1[KSPLIT * B_ * G3_];
__device__ float g_p_base[KSPLIT * B_ * E_];
__device__ float g_p_gh2[KSPLIT * B_ * G3_];
__device__ float g_p_gi2[KSPLIT * B_ * G3_];
__device__ unsigned long long g_arrive = 0ULL;    // monotonic ticket (never reset; replay-safe)

// ---------------- math helpers ----------------
__device__ __forceinline__ float fast_tanh(float x) {
    float e = __expf(2.0f * x);
    return 1.0f - __fdividef(2.0f, e + 1.0f);
}
__device__ __forceinline__ float fast_sigmoid(float x) {
    return __fdividef(1.0f, 1.0f + __expf(-x));
}
__device__ __forceinline__ float tanh_hw(float x) {   // MUFU.TANH
    float y;
    asm("tanh.approx.f32 %0, %1;" : "=f"(y) : "f"(x));
    return y;
}

// ---------------- packed f32x2 FMA helpers ----------------
__device__ __forceinline__ void ffma2(unsigned long long& acc, unsigned long long a,
                                      unsigned long long b) {
    asm("fma.rn.f32x2 %0, %1, %2, %0;" : "+l"(acc) : "l"(a), "l"(b));
}
__device__ __forceinline__ unsigned long long splat2(float x) {
    unsigned long long r;
    unsigned u = __float_as_uint(x);
    asm("mov.b64 %0, {%1, %1};" : "=l"(r) : "r"(u));
    return r;
}
__device__ __forceinline__ float2 unpack2(unsigned long long v) {
    unsigned lo, hi;
    asm("mov.b64 {%0, %1}, %2;" : "=r"(lo), "=r"(hi) : "l"(v));
    return make_float2(__uint_as_float(lo), __uint_as_float(hi));
}

// ---------------- grid barrier: libcu++ device-scope release/acquire ----------------
__device__ __forceinline__ void gsync() {
    __syncthreads();
    if (threadIdx.x == 0) {
        cuda::atomic_ref<unsigned long long, cuda::thread_scope_device> a(g_arrive);
        unsigned long long nb = (unsigned long long)gridDim.x;
        unsigned long long tk = a.fetch_add(1ULL, cuda::memory_order_acq_rel) + 1ULL;
        unsigned long long target = ((tk + nb - 1ULL) / nb) * nb;
        while (a.load(cuda::memory_order_acquire) < target) {}
    }
    __syncthreads();
}

// ---------------- init: state, coverage, x_indexes output ----------------
__global__ void k_init(const float* __restrict__ init_state,
                       const float* __restrict__ init_cov,
                       const int* __restrict__ x_index,
                       float* __restrict__ out_xi) {
    int i = blockIdx.x * blockDim.x + threadIdx.x;
    if (i < B_ * H_) g_h[i] = init_state[i];
    if (i < B_ * S_) g_cov[i] = init_cov[i];
    for (int j = i; j < T_ * B_ * S_; j += gridDim.x * blockDim.x) {
        int s = j % S_;
        int b = (j / S_) % B_;
        out_xi[j] = (float)x_index[s * B_ + b];
    }
}

// ---------------- big SGEMM: C = A @ W^T (+bias), BK=16 dbl-buffered, FFMA2 ----------------
__global__ __launch_bounds__(256) void k_sgemm_nt(
    const float* __restrict__ A, const float* __restrict__ W,
    const float* __restrict__ bias, float* __restrict__ C,
    int M, int N, int K) {
    __shared__ __align__(16) float As[2][16][128];
    __shared__ __align__(16) float Bs[2][16][128];
    const int m0 = blockIdx.y * 128;
    const int n0 = blockIdx.x * 128;
    const int tid = threadIdx.x;
    const int tm = (tid / 16) * 8;
    const int tn = (tid % 16) * 8;
    const int lr = tid >> 1;
    const int lc = (tid & 1) * 8;

    unsigned long long accp[8][4];
#pragma unroll
    for (int i = 0; i < 8; i++)
#pragma unroll
        for (int j = 0; j < 4; j++) accp[i][j] = 0ULL;

    const float* Ap = A + (size_t)(m0 + lr) * K + lc;
    const float* Wp = W + (size_t)(n0 + lr) * K + lc;

    float4 pa0 = *(const float4*)(Ap + 0);
    float4 pa1 = *(const float4*)(Ap + 4);
    float4 pb0 = *(const float4*)(Wp + 0);
    float4 pb1 = *(const float4*)(Wp + 4);

    As[0][lc + 0][lr] = pa0.x; As[0][lc + 1][lr] = pa0.y; As[0][lc + 2][lr] = pa0.z; As[0][lc + 3][lr] = pa0.w;
    As[0][lc + 4][lr] = pa1.x; As[0][lc + 5][lr] = pa1.y; As[0][lc + 6][lr] = pa1.z; As[0][lc + 7][lr] = pa1.w;
    Bs[0][lc + 0][lr] = pb0.x; Bs[0][lc + 1][lr] = pb0.y; Bs[0][lc + 2][lr] = pb0.z; Bs[0][lc + 3][lr] = pb0.w;
    Bs[0][lc + 4][lr] = pb1.x; Bs[0][lc + 5][lr] = pb1.y; Bs[0][lc + 6][lr] = pb1.z; Bs[0][lc + 7][lr] = pb1.w;
    __syncthreads();

    const int nt = K / 16;
    int buf = 0;
    for (int t = 0; t < nt; t++) {
        if (t + 1 < nt) {
            int k0 = (t + 1) * 16;
            pa0 = *(const float4*)(Ap + k0);
            pa1 = *(const float4*)(Ap + k0 + 4);
            pb0 = *(const float4*)(Wp + k0);
            pb1 = *(const float4*)(Wp + k0 + 4);
        }
#pragma unroll
        for (int kk = 0; kk < 16; kk++) {
            float4 a0 = *(const float4*)&As[buf][kk][tm];
            float4 a1 = *(const float4*)&As[buf][kk][tm + 4];
            ulonglong2 b01 = *(const ulonglong2*)&Bs[buf][kk][tn];
            ulonglong2 b23 = *(const ulonglong2*)&Bs[buf][kk][tn + 4];
            unsigned long long bp0 = b01.x, bp1 = b01.y, bp2 = b23.x, bp3 = b23.y;
            float av[8] = {a0.x, a0.y, a0.z, a0.w, a1.x, a1.y, a1.z, a1.w};
#pragma unroll
            for (int i = 0; i < 8; i++) {
                unsigned long long ap = splat2(av[i]);
                ffma2(accp[i][0], ap, bp0);
                ffma2(accp[i][1], ap, bp1);
                ffma2(accp[i][2], ap, bp2);
                ffma2(accp[i][3], ap, bp3);
            }
        }
        if (t + 1 < nt) {
            int nb = buf ^ 1;
            As[nb][lc + 0][lr] = pa0.x; As[nb][lc + 1][lr] = pa0.y; As[nb][lc + 2][lr] = pa0.z; As[nb][lc + 3][lr] = pa0.w;
            As[nb][lc + 4][lr] = pa1.x; As[nb][lc + 5][lr] = pa1.y; As[nb][lc + 6][lr] = pa1.z; As[nb][lc + 7][lr] = pa1.w;
            Bs[nb][lc + 0][lr] = pb0.x; Bs[nb][lc + 1][lr] = pb0.y; Bs[nb][lc + 2][lr] = pb0.z; Bs[nb][lc + 3][lr] = pb0.w;
            Bs[nb][lc + 4][lr] = pb1.x; Bs[nb][lc + 5][lr] = pb1.y; Bs[nb][lc + 6][lr] = pb1.z; Bs[nb][lc + 7][lr] = pb1.w;
            __syncthreads();
            buf = nb;
        }
    }
    float bfrag[8];
#pragma unroll
    for (int j = 0; j < 8; j++) bfrag[j] = bias ? bias[n0 + tn + j] : 0.0f;
#pragma unroll
    for (int i = 0; i < 8; i++) {
        size_t row = (size_t)(m0 + tm + i) * N + n0 + tn;
#pragma unroll
        for (int jp = 0; jp < 4; jp++) {
            float2 f = unpack2(accp[i][jp]);
            C[row + 2 * jp]     = f.x + bfrag[2 * jp];
            C[row + 2 * jp + 1] = f.y + bfrag[2 * jp + 1];
        }
    }
}

// ---------------- small batch-32 split-K tile (FFMA2 inner loop) ----------------
__device__ __forceinline__ void small_tile(
    const float* __restrict__ X, const float* __restrict__ W,
    float* __restrict__ part, int N, int n0, int Kstride, int KC, int kc,
    float (*ws)[33], float (*xs)[36]) {
    const int k0 = kc * KC;
    const int tid = threadIdx.x;
    const int j = tid & 127;
    const int bg = tid >> 7;

    unsigned long long accp[8];
#pragma unroll
    for (int u = 0; u < 8; u++) accp[u] = 0ULL;

    for (int kt = 0; kt < KC; kt += 32) {
        {
            int r = tid >> 1;
            int cb = (tid & 1) * 16;
#pragma unroll
            for (int u = 0; u < 4; u++) {
                float4 v = *(const float4*)&W[(size_t)(n0 + r) * Kstride + k0 + kt + cb + u * 4];
                ws[r][cb + u * 4 + 0] = v.x; ws[r][cb + u * 4 + 1] = v.y;
                ws[r][cb + u * 4 + 2] = v.z; ws[r][cb + u * 4 + 3] = v.w;
            }
        }
        {
            int b = tid >> 3;
            int c = (tid & 7) * 4;
            float4 v = __ldcg((const float4*)&X[(size_t)b * Kstride + k0 + kt + c]);
            xs[c + 0][b] = v.x; xs[c + 1][b] = v.y; xs[c + 2][b] = v.z; xs[c + 3][b] = v.w;
        }
        __syncthreads();
#pragma unroll
        for (int kk = 0; kk < 32; kk++) {
            unsigned long long wp = splat2(ws[j][kk]);
            const ulonglong2* xr = (const ulonglong2*)&xs[kk][bg * 16];
            ulonglong2 q0 = xr[0], q1 = xr[1], q2 = xr[2], q3 = xr[3];
            ffma2(accp[0], wp, q0.x); ffma2(accp[1], wp, q0.y);
            ffma2(accp[2], wp, q1.x); ffma2(accp[3], wp, q1.y);
            ffma2(accp[4], wp, q2.x); ffma2(accp[5], wp, q2.y);
            ffma2(accp[6], wp, q3.x); ffma2(accp[7], wp, q3.y);
        }
        __syncthreads();
    }
    float* p = part + ((size_t)kc * B_ + bg * 16) * N + n0 + j;
#pragma unroll
    for (int u = 0; u < 8; u++) {
        float2 f = unpack2(accp[u]);
        __stcg(&p[(size_t)(2 * u) * N],     f.x);
        __stcg(&p[(size_t)(2 * u + 1) * N], f.y);
    }
}

// ---------------- ONE kernel per step: P1,P2,P3,P5,P6,P7,P8 (P4 folded into P5) ----------------
__global__ __launch_bounds__(NTHREADS, 3) void k_step(
    const float* __restrict__ enc, const float* __restrict__ x_mask,
    const float* __restrict__ y_mask,
    const float* __restrict__ W_c, const float* __restrict__ b_attn,
    const float* __restrict__ V,
    const float* __restrict__ w_hh1, const float* __restrict__ b_hh1,
    const float* __restrict__ W_s, const float* __restrict__ w_hh2,
    const float* __restrict__ b_ih2, const float* __restrict__ b_hh2,
    const float* __restrict__ w_ih2,
    float* __restrict__ out_h, float* __restrict__ out_ctx,
    float* __restrict__ out_aw, float* __restrict__ out_cov, int t) {

    __shared__ __align__(16) float sh_ws[128][33];
    __shared__ __align__(16) float sh_xs[32][36];
    __shared__ __align__(16) float sh_base[E_];
    __shared__ __align__(16) float sh_wc[E_];
    __shared__ __align__(16) float sh_v[E_];
    __shared__ float sh_aw[S_];
    __shared__ __align__(16) float4 sh_p4[NTHREADS];
    __shared__ float sh_red[8];
    __shared__ float sh_bc;

    const int tid = threadIdx.x;
    const int nb = gridDim.x;
    const int gstride = nb * NTHREADS;

    for (int i = tid; i < E_; i += NTHREADS) {
        sh_wc[i] = W_c[i];
        sh_v[i]  = V[i];
    }

    // ---- P1: gh1 partials = h @ w_hh1^T ---- (g_h from prior LAUNCH)
    for (int task = blockIdx.x; task < 12 * KSPLIT; task += nb)
        small_tile(g_h, w_hh1, g_p_gh1, G3_, (task % 12) * 128, H_, H_ / KSPLIT,
                   task / 12, sh_ws, sh_xs);
    gsync();

    // ---- P2: GRU1 finish -> s1 ----
    for (int i = blockIdx.x * NTHREADS + tid; i < B_ * H_; i += gstride) {
        int b = i / H_, idx = i % H_;
        float h = __ldcg(&g_h[i]);
        const float* gi = g_gi1 + ((size_t)t * B_ + b) * G3_;
        float gir = gi[idx], giz = gi[H_ + idx], gin = gi[2 * H_ + idx];
        float ghr = b_hh1[idx], ghz = b_hh1[H_ + idx], ghn = b_hh1[2 * H_ + idx];
#pragma unroll
        for (int c = 0; c < KSPLIT; c++) {
            const float* p = g_p_gh1 + ((size_t)c * B_ + b) * G3_;
            ghr += __ldcg(&p[idx]); ghz += __ldcg(&p[H_ + idx]); ghn += __ldcg(&p[2 * H_ + idx]);
        }
        float r = fast_sigmoid(gir + ghr);
        float z = fast_sigmoid(giz + ghz);
        float n = fast_tanh(gin + r * ghn);
        float s = (1.0f - z) * n + z * h;
        float ym = y_mask[t * B_ + b];
        __stcg(&g_s1[i], ym * s + (1.0f - ym) * h);
    }
    gsync();

    // ---- P3: dual partials: base = s1@W_s^T, gh2 = s1@w_hh2^T ----
    for (int task = blockIdx.x; task < 20 * KSPLIT; task += nb) {
        int nt = task % 20, kc = task / 20;
        if (nt < 8)
            small_tile(g_s1, W_s, g_p_base, E_, nt * 128, H_, H_ / KSPLIT, kc, sh_ws, sh_xs);
        else
            small_tile(g_s1, w_hh2, g_p_gh2, G3_, (nt - 8) * 128, H_, H_ / KSPLIT, kc, sh_ws, sh_xs);
    }
    gsync();

    // ---- P5: attention scores (base reduce folded into staging; hw tanh) ----
    for (int task = blockIdx.x; task < B_ * 10; task += nb) {
        int b = task % B_;
        int sc = task / B_;
        // stage sh_base = b_attn + sum_c p_base[c][b][:]  (E/4 float4s, 1 per thread)
        {
            int f4 = tid;  // 0..255 ; E_/4 == 256
            float4 v = *(const float4*)&b_attn[f4 * 4];
#pragma unroll
            for (int c = 0; c < KSPLIT; c++) {
                float4 p = __ldcg((const float4*)&g_p_base[((size_t)c * B_ + b) * E_ + f4 * 4]);
                v.x += p.x; v.y += p.y; v.z += p.z; v.w += p.w;
            }
            *(float4*)&sh_base[f4 * 4] = v;
        }
        __syncthreads();
        int warp = tid >> 5, lane = tid & 31;
        for (int si = warp; si < 40; si += 8) {
            int s = sc * 40 + si;
            float cov = __ldcg(&g_cov[b * S_ + s]);
            const float4* wh = (const float4*)&g_Wh[(size_t)(s * B_ + b) * E_];
            float acc = 0.0f;
#pragma unroll
            for (int i2 = 0; i2 < 8; i2++) {
                int f = i2 * 32 + lane;
                float4 w4 = __ldcs(&wh[f]);          // streaming: don't pollute L2
                float4 b4 = *(const float4*)&sh_base[f * 4];
                float4 c4 = *(const float4*)&sh_wc[f * 4];
                float4 v4 = *(const float4*)&sh_v[f * 4];
                acc += tanh_hw(w4.x + b4.x + cov * c4.x) * v4.x;
                acc += tanh_hw(w4.y + b4.y + cov * c4.y) * v4.y;
                acc += tanh_hw(w4.z + b4.z + cov * c4.z) * v4.z;
                acc += tanh_hw(w4.w + b4.w + cov * c4.w) * v4.w;
            }
#pragma unroll
            for (int o = 16; o > 0; o >>= 1) acc += __shfl_xor_sync(0xffffffffu, acc, o);
            if (lane == 0) {
                float m = x_mask[s * B_ + b];
                __stcg(&g_score[b * S_ + s], (m == 0.0f) ? -1e9f : m * acc);
            }
        }
        __syncthreads();
    }
    gsync();

    // ---- P6: softmax + ctx (enc L2-cached float4 loads) ----
    for (int task = blockIdx.x; task < B_ * 8; task += nb) {
        int b = task >> 3, ec = task & 7;
        int lane = tid & 31, warp = tid >> 5;
        float v0 = __ldcg(&g_score[b * S_ + tid]);
        float v1 = (tid + 256 < S_) ? __ldcg(&g_score[b * S_ + tid + 256]) : -3.0e38f;
        float m = fmaxf(v0, v1);
#pragma unroll
        for (int o = 16; o > 0; o >>= 1) m = fmaxf(m, __shfl_xor_sync(0xffffffffu, m, o));
        if (lane == 0) sh_red[warp] = m;
        __syncthreads();
        if (tid == 0) {
            float x = sh_red[0];
#pragma unroll
            for (int i = 1; i < 8; i++) x = fmaxf(x, sh_red[i]);
            sh_bc = x;
        }
        __syncthreads();
        float mx = sh_bc;
        float e0 = __expf(v0 - mx);
        float e1 = (tid + 256 < S_) ? __expf(v1 - mx) : 0.0f;
        float sm = e0 + e1;
#pragma unroll
        for (int o = 16; o > 0; o >>= 1) sm += __shfl_xor_sync(0xffffffffu, sm, o);
        __syncthreads();
        if (lane == 0) sh_red[warp] = sm;
        __syncthreads();
        if (tid == 0) {
            float x = 0.0f;
#pragma unroll
            for (int i = 0; i < 8; i++) x += sh_red[i];
            sh_bc = __fdividef(1.0f, x);
        }
        __syncthreads();
        float inv = sh_bc;
        sh_aw[tid] = e0 * inv;
        if (tid + 256 < S_) sh_aw[tid + 256] = e1 * inv;
        __syncthreads();

        if (ec == 0) {
            for (int idx = tid; idx < S_; idx += NTHREADS) {
                float aw = sh_aw[idx];
                out_aw[((size_t)t * B_ + b) * S_ + idx] = aw;
                float c = __ldcg(&g_cov[b * S_ + idx]);
                out_cov[((size_t)t * B_ + b) * S_ + idx] = c;  // coverage BEFORE update
                __stcg(&g_cov[b * S_ + idx], c + aw);
            }
        }

        // ctx: 32 float4-columns x 8 s-groups of 50
        int f4 = tid & 31, sg = tid >> 5;
        const float4* ep = (const float4*)(enc + (size_t)b * E_ + ec * 128) + f4;
        float4 acc = make_float4(0.0f, 0.0f, 0.0f, 0.0f);
        int s0 = sg * 50;
#pragma unroll 10
        for (int s = s0; s < s0 + 50; s++) {
            float a = sh_aw[s];
            float4 v = __ldcg(&ep[(size_t)s * (B_ * E_ / 4)]);
            acc.x += a * v.x; acc.y += a * v.y; acc.z += a * v.z; acc.w += a * v.w;
        }
        sh_p4[tid] = acc;
        __syncthreads();
        if (tid < 32) {
            float4 r = sh_p4[tid];
#pragma unroll
            for (int g = 1; g < 8; g++) {
                float4 q = sh_p4[g * 32 + tid];
                r.x += q.x; r.y += q.y; r.z += q.z; r.w += q.w;
            }
            int e = ec * 128 + tid * 4;
            __stcg((float4*)&g_ctx[b * E_ + e], r);
            *(float4*)&out_ctx[((size_t)t * B_ + b) * E_ + e] = r;
        }
        __syncthreads();
    }
    gsync();

    // ---- P7: gi2 partials = ctx @ w_ih2^T ----
    for (int task = blockIdx.x; task < 12 * KSPLIT; task += nb)
        small_tile(g_ctx, w_ih2, g_p_gi2, G3_, (task % 12) * 128, E_, E_ / KSPLIT,
                   task / 12, sh_ws, sh_xs);
    gsync();

    // ---- P8: GRU2 finish -> h, out_h ----
    for (int i = blockIdx.x * NTHREADS + tid; i < B_ * H_; i += gstride) {
        int b = i / H_, idx = i % H_;
        float s1 = __ldcg(&g_s1[i]);
        float gir = b_ih2[idx], giz = b_ih2[H_ + idx], gin = b_ih2[2 * H_ + idx];
        float ghr = b_hh2[idx], ghz = b_hh2[H_ + idx], ghn = b_hh2[2 * H_ + idx];
#pragma unroll
        for (int c = 0; c < KSPLIT; c++) {
            const float* pi = g_p_gi2 + ((size_t)c * B_ + b) * G3_;
            const float* ph = g_p_gh2 + ((size_t)c * B_ + b) * G3_;
            gir += __ldcg(&pi[idx]); giz += __ldcg(&pi[H_ + idx]); gin += __ldcg(&pi[2 * H_ + idx]);
            ghr += __ldcg(&ph[idx]); ghz += __ldcg(&ph[H_ + idx]); ghn += __ldcg(&ph[2 * H_ + idx]);
        }
        float r = fast_sigmoid(gir + ghr);
        float z = fast_sigmoid(giz + ghz);
        float n = fast_tanh(gin + r * ghn);
        float s = (1.0f - z) * n + z * s1;
        float ym = y_mask[t * B_ + b];
        float s2 = ym * s + (1.0f - ym) * s1;
        __stcg(&g_h[i], s2);
        out_h[((size_t)t * B_ + b) * H_ + idx] = s2;
    }
    // launch boundary provides the final sync
}

// ---------------- host launcher ----------------
extern "C" void kernel_launch(void* const* d_in, const int* in_sizes, int n_in,
                              void* d_out, int out_size) {
    const float* emb        = (const float*)d_in[0];
    const float* enc        = (const float*)d_in[1];
    const float* init_state = (const float*)d_in[2];
    const float* x_mask     = (const float*)d_in[3];
    const float* y_mask     = (const float*)d_in[4];
    const int*   x_index    = (const int*)  d_in[5];
    const float* init_cov   = (const float*)d_in[6];
    const float* W_h        = (const float*)d_in[7];
    const float* W_s        = (const float*)d_in[8];
    const float* W_c        = (const float*)d_in[9];
    const float* b_attn     = (const float*)d_in[10];
    const float* V          = (const float*)d_in[11];
    const float* w_ih1      = (const float*)d_in[12];
    const float* w_hh1      = (const float*)d_in[13];
    const float* b_ih1      = (const float*)d_in[14];
    const float* b_hh1      = (const float*)d_in[15];
    const float* w_ih2      = (const float*)d_in[16];
    const float* w_hh2      = (const float*)d_in[17];
    const float* b_ih2      = (const float*)d_in[18];
    const float* b_hh2      = (const float*)d_in[19];

    float* out     = (float*)d_out;
    float* out_h   = out;                               // (T,B,H)
    float* out_ctx = out_h + (size_t)T_ * B_ * H_;      // (T,B,E)
    float* out_aw  = out_ctx + (size_t)T_ * B_ * E_;    // (T,B,S)
    float* out_xi  = out_aw + (size_t)T_ * B_ * S_;     // (T,B,S)
    float* out_cov = out_xi + (size_t)T_ * B_ * S_;     // (T,B,S)

    float *p_Wh, *p_gi1;
    cudaGetSymbolAddress((void**)&p_Wh, g_Wh);
    cudaGetSymbolAddress((void**)&p_gi1, g_gi1);

    k_init<<<256, 256>>>(init_state, init_cov, x_index, out_xi);

    // Wh_enc = enc @ W_h^T : M=12800, N=1024, K=1024
    k_sgemm_nt<<<dim3(E_ / 128, (S_ * B_) / 128), 256>>>(enc, W_h, nullptr, p_Wh, S_ * B_, E_, E_);
    // gi1 = emb @ w_ih1^T + b_ih1 : M=2048, N=1536, K=128
    k_sgemm_nt<<<dim3(G3_ / 128, (T_ * B_) / 128), 256>>>(emb, w_ih1, b_ih1, p_gi1, T_ * B_, G3_, I_);

    // 3 co-resident blocks per SM
    int dev = 0;
    cudaGetDevice(&dev);
    int sms = 148;
    cudaDeviceGetAttribute(&sms, cudaDevAttrMultiProcessorCount, dev);
    int NB = sms * 3;

    for (int t = 0; t < T_; t++) {
        k_step<<<NB, NTHREADS>>>(enc, x_mask, y_mask, W_c, b_attn, V,
                                 w_hh1, b_hh1, W_s, w_hh2, b_ih2, b_hh2, w_ih2,
                                 out_h, out_ctx, out_aw, out_cov, t);
    }
}